// round 1
// baseline (speedup 1.0000x reference)
#include <cuda_runtime.h>

// ---------------- problem constants ----------------
#define LNUM 8
#define BNUM 1024
#define DNUM 1024
#define FNUM 8192

// output layout (flattened tuple concat, all f32):
// [0, L*B*D)                       recons
// [L*B*D, L*B*D + L*B*F)           feats
// then: loss, recon_loss, sparsity_loss, per_layer_l0[8]
static const long long FEATS_OFF = (long long)LNUM * BNUM * DNUM;          // 8388608
static const long long LOSS_OFF  = FEATS_OFF + (long long)LNUM * BNUM * FNUM; // 75497472

// ---------------- tiling ----------------
#define TM 128
#define TN 128
#define KT 16

// ---------------- global accumulators (no allocs allowed) ----------------
__device__ double g_sp_sum;                 // sum of feats (== sum |feats| since relu>=0)
__device__ double g_sq_sum;                 // sum of (recons - target)^2
__device__ unsigned long long g_cnt[LNUM];  // per-layer count of feats > 0

__global__ void init_acc_kernel() {
    g_sp_sum = 0.0;
    g_sq_sum = 0.0;
    for (int i = 0; i < LNUM; ++i) g_cnt[i] = 0ull;
}

// ---------------- shared GEMM mainloop ----------------
// C[m, n] += sum_k A[m, k] * W[n, k]; A, W both row-major with row stride == KDIM.
// A must point at the CTA's first row (already offset by m0*KDIM), W likewise (n0*KDIM).
// 256 threads, each computes an 8x8 micro-tile of the 128x128 CTA tile.
template <int KDIM>
__device__ __forceinline__ void gemm_acc(const float* __restrict__ A,
                                         const float* __restrict__ W,
                                         float (&acc)[8][8],
                                         float (*As)[TM + 4],
                                         float (*Ws)[TN + 4]) {
    const int tid  = threadIdx.x;
    const int lrow = tid >> 2;         // 0..63
    const int lk   = (tid & 3) * 4;    // 0,4,8,12 (float4 along K)
    const int tx   = tid & 15;
    const int ty   = tid >> 4;
    const int rm   = ty * 8;
    const int rn   = tx * 8;

    const float* a0p = A + (long long)lrow * KDIM + lk;
    const float* a1p = A + (long long)(lrow + 64) * KDIM + lk;
    const float* w0p = W + (long long)lrow * KDIM + lk;
    const float* w1p = W + (long long)(lrow + 64) * KDIM + lk;

    // prefetch first K-tile into registers
    float4 a0 = *(const float4*)(a0p);
    float4 a1 = *(const float4*)(a1p);
    float4 w0 = *(const float4*)(w0p);
    float4 w1 = *(const float4*)(w1p);

    for (int k0 = 0; k0 < KDIM; k0 += KT) {
        __syncthreads();  // prior compute done before overwriting smem
        As[lk + 0][lrow]      = a0.x; As[lk + 1][lrow]      = a0.y;
        As[lk + 2][lrow]      = a0.z; As[lk + 3][lrow]      = a0.w;
        As[lk + 0][lrow + 64] = a1.x; As[lk + 1][lrow + 64] = a1.y;
        As[lk + 2][lrow + 64] = a1.z; As[lk + 3][lrow + 64] = a1.w;
        Ws[lk + 0][lrow]      = w0.x; Ws[lk + 1][lrow]      = w0.y;
        Ws[lk + 2][lrow]      = w0.z; Ws[lk + 3][lrow]      = w0.w;
        Ws[lk + 0][lrow + 64] = w1.x; Ws[lk + 1][lrow + 64] = w1.y;
        Ws[lk + 2][lrow + 64] = w1.z; Ws[lk + 3][lrow + 64] = w1.w;
        __syncthreads();

        if (k0 + KT < KDIM) {  // register prefetch of the next K-tile, overlapped with FFMAs
            a0 = *(const float4*)(a0p + k0 + KT);
            a1 = *(const float4*)(a1p + k0 + KT);
            w0 = *(const float4*)(w0p + k0 + KT);
            w1 = *(const float4*)(w1p + k0 + KT);
        }

#pragma unroll
        for (int k = 0; k < KT; ++k) {
            float4 av0 = *(const float4*)&As[k][rm];
            float4 av1 = *(const float4*)&As[k][rm + 4];
            float4 bv0 = *(const float4*)&Ws[k][rn];
            float4 bv1 = *(const float4*)&Ws[k][rn + 4];
            float av[8] = {av0.x, av0.y, av0.z, av0.w, av1.x, av1.y, av1.z, av1.w};
            float bv[8] = {bv0.x, bv0.y, bv0.z, bv0.w, bv1.x, bv1.y, bv1.z, bv1.w};
#pragma unroll
            for (int i = 0; i < 8; ++i)
#pragma unroll
                for (int j = 0; j < 8; ++j)
                    acc[i][j] = fmaf(av[i], bv[j], acc[i][j]);
        }
    }
}

// ---------------- encoder: feats = relu(resid @ enc_w^T + b), fused L1/L0 sums ----------------
__global__ __launch_bounds__(256) void encoder_kernel(const float* __restrict__ resid,   // [L,B,D]
                                                      const float* __restrict__ enc_w,   // [L,F,D]
                                                      const float* __restrict__ enc_b,   // [L,F]
                                                      float* __restrict__ out) {
    __shared__ float As[KT][TM + 4];
    __shared__ float Ws[KT][TN + 4];
    __shared__ float s_sp[8];
    __shared__ int   s_cnt[8];

    const int l  = blockIdx.z;
    const int m0 = blockIdx.y * TM;  // b
    const int n0 = blockIdx.x * TN;  // f

    float acc[8][8];
#pragma unroll
    for (int i = 0; i < 8; ++i)
#pragma unroll
        for (int j = 0; j < 8; ++j) acc[i][j] = 0.0f;

    gemm_acc<DNUM>(resid + ((long long)l * BNUM + m0) * DNUM,
                   enc_w + ((long long)l * FNUM + n0) * DNUM, acc, As, Ws);

    const int tid = threadIdx.x;
    const int tx  = tid & 15, ty = tid >> 4;
    const int rm  = ty * 8, rn = tx * 8;

    float bias[8];
#pragma unroll
    for (int j = 0; j < 8; ++j) bias[j] = enc_b[(long long)l * FNUM + n0 + rn + j];

    float sp = 0.0f;
    int   cnt = 0;
#pragma unroll
    for (int i = 0; i < 8; ++i) {
        float v[8];
#pragma unroll
        for (int j = 0; j < 8; ++j) {
            float x = acc[i][j] + bias[j];
            x = fmaxf(x, 0.0f);
            v[j] = x;
            sp += x;
            cnt += (x > 0.0f) ? 1 : 0;
        }
        long long row = (long long)l * BNUM + (m0 + rm + i);
        float* po = out + FEATS_OFF + row * FNUM + n0 + rn;
        *(float4*)(po)     = make_float4(v[0], v[1], v[2], v[3]);
        *(float4*)(po + 4) = make_float4(v[4], v[5], v[6], v[7]);
    }

    // block reduce -> one atomic per block
#pragma unroll
    for (int o = 16; o > 0; o >>= 1) {
        sp  += __shfl_down_sync(0xffffffffu, sp, o);
        cnt += __shfl_down_sync(0xffffffffu, cnt, o);
    }
    const int lane = tid & 31, warp = tid >> 5;
    if (lane == 0) { s_sp[warp] = sp; s_cnt[warp] = cnt; }
    __syncthreads();
    if (tid == 0) {
        float tsp = 0.0f; int tc = 0;
        for (int w = 0; w < 8; ++w) { tsp += s_sp[w]; tc += s_cnt[w]; }
        atomicAdd(&g_sp_sum, (double)tsp);
        atomicAdd(&g_cnt[l], (unsigned long long)tc);
    }
}

// ---------------- decoder: recons[t] = sum_{s in {t-2..t}} feats[s] @ dec_w[p(s,t)]^T ----------
// pair index for (src=s, tgt=t): base(s) + (t - s); base(s) = 3s for s<=5, 2s+6 for s>=6.
__global__ __launch_bounds__(256) void decoder_kernel(const float* __restrict__ feats,   // [L,B,F]
                                                      const float* __restrict__ dec_w,   // [P,D,F]
                                                      const float* __restrict__ tgt,     // [L,B,D]
                                                      float* __restrict__ out) {
    __shared__ float As[KT][TM + 4];
    __shared__ float Ws[KT][TN + 4];
    __shared__ float s_sq[8];

    const int t  = blockIdx.z;
    const int m0 = blockIdx.y * TM;  // b
    const int n0 = blockIdx.x * TN;  // d

    float acc[8][8];
#pragma unroll
    for (int i = 0; i < 8; ++i)
#pragma unroll
        for (int j = 0; j < 8; ++j) acc[i][j] = 0.0f;

    const int s_lo = (t >= 2) ? (t - 2) : 0;
    for (int s = s_lo; s <= t; ++s) {
        const int base = (s <= 5) ? (3 * s) : (2 * s + 6);
        const int p    = base + (t - s);
        gemm_acc<FNUM>(feats + ((long long)s * BNUM + m0) * FNUM,
                       dec_w + ((long long)p * DNUM + n0) * FNUM, acc, As, Ws);
    }

    const int tid = threadIdx.x;
    const int tx  = tid & 15, ty = tid >> 4;
    const int rm  = ty * 8, rn = tx * 8;

    float sq = 0.0f;
#pragma unroll
    for (int i = 0; i < 8; ++i) {
        long long row = (long long)t * BNUM + (m0 + rm + i);
        const float* pt = tgt + row * DNUM + n0 + rn;
        float4 t0 = *(const float4*)(pt);
        float4 t1 = *(const float4*)(pt + 4);
        float tv[8] = {t0.x, t0.y, t0.z, t0.w, t1.x, t1.y, t1.z, t1.w};
        float v[8];
#pragma unroll
        for (int j = 0; j < 8; ++j) {
            v[j] = acc[i][j];
            float d = v[j] - tv[j];
            sq = fmaf(d, d, sq);
        }
        float* po = out + row * DNUM + n0 + rn;  // recons at offset 0
        *(float4*)(po)     = make_float4(v[0], v[1], v[2], v[3]);
        *(float4*)(po + 4) = make_float4(v[4], v[5], v[6], v[7]);
    }

#pragma unroll
    for (int o = 16; o > 0; o >>= 1) sq += __shfl_down_sync(0xffffffffu, sq, o);
    const int lane = tid & 31, warp = tid >> 5;
    if (lane == 0) s_sq[warp] = sq;
    __syncthreads();
    if (tid == 0) {
        float tsq = 0.0f;
        for (int w = 0; w < 8; ++w) tsq += s_sq[w];
        atomicAdd(&g_sq_sum, (double)tsq);
    }
}

// ---------------- finalize scalars ----------------
__global__ void finalize_kernel(float* __restrict__ out) {
    const int tid = threadIdx.x;
    if (tid == 0) {
        double rl = g_sq_sum / ((double)LNUM * (double)BNUM * (double)DNUM);
        double sl = 1e-4 * (g_sp_sum / ((double)LNUM * (double)BNUM * (double)FNUM));
        out[LOSS_OFF + 0] = (float)(rl + sl);
        out[LOSS_OFF + 1] = (float)rl;
        out[LOSS_OFF + 2] = (float)sl;
    }
    if (tid < LNUM) out[LOSS_OFF + 3 + tid] = (float)((double)g_cnt[tid] / (double)BNUM);
}

// ---------------- entry point ----------------
extern "C" void kernel_launch(void* const* d_in, const int* in_sizes, int n_in,
                              void* d_out, int out_size) {
    (void)in_sizes; (void)n_in; (void)out_size;
    const float* resid   = (const float*)d_in[0];  // residual_streams [L,B,D]
    const float* targets = (const float*)d_in[1];  // moe_targets     [L,B,D]
    const float* enc_w   = (const float*)d_in[2];  // [L,F,D]
    const float* enc_b   = (const float*)d_in[3];  // [L,F]
    const float* dec_w   = (const float*)d_in[4];  // [P,D,F]
    float* out = (float*)d_out;

    init_acc_kernel<<<1, 1>>>();

    dim3 blk(256);
    dim3 genc(FNUM / TN, BNUM / TM, LNUM);  // (64, 8, 8)
    encoder_kernel<<<genc, blk>>>(resid, enc_w, enc_b, out);

    dim3 gdec(DNUM / TN, BNUM / TM, LNUM);  // (8, 8, 8)
    decoder_kernel<<<gdec, blk>>>(out + FEATS_OFF, dec_w, targets, out);

    finalize_kernel<<<1, 32>>>(out);
}

// round 3
// speedup vs baseline: 2.2676x; 2.2676x over previous
#include <cuda_runtime.h>
#include <cuda_bf16.h>
#include <cstdint>

// ---------------- problem constants ----------------
#define LNUM 8
#define BNUM 1024
#define DNUM 1024
#define FNUM 8192
#define KC   32              // fp32 K elements per chunk
#define STAGE_B32 8192       // 32KB per stage (Ah 8K | Al 8K | Bh 8K | Bl 8K)
#define SMEM_DYN  65536      // 2 stages

static const long long FEATS_OFF = (long long)LNUM * BNUM * DNUM;               // 8388608
static const long long LOSS_OFF  = FEATS_OFF + (long long)LNUM * BNUM * FNUM;   // 75497472

// ---------------- global accumulators ----------------
__device__ double g_sp_sum;
__device__ double g_sq_sum;
__device__ unsigned long long g_cnt[LNUM];

__global__ void init_acc_kernel() {
    g_sp_sum = 0.0;
    g_sq_sum = 0.0;
    for (int i = 0; i < LNUM; ++i) g_cnt[i] = 0ull;
}

// ---------------- small helpers ----------------
__device__ __forceinline__ uint32_t smem_u32(const void* p) {
    uint32_t a;
    asm("{ .reg .u64 t; cvta.to.shared.u64 t, %1; cvt.u32.u64 %0, t; }" : "=r"(a) : "l"(p));
    return a;
}
__device__ __forceinline__ void lds128(uint32_t (&r)[4], uint32_t addr) {
    asm volatile("ld.shared.v4.b32 {%0,%1,%2,%3}, [%4];"
        : "=r"(r[0]), "=r"(r[1]), "=r"(r[2]), "=r"(r[3]) : "r"(addr));
}
__device__ __forceinline__ void mma16816(float (&c)[4], const uint32_t (&a)[4],
                                         uint32_t b0, uint32_t b1) {
    asm volatile("mma.sync.aligned.m16n8k16.row.col.f32.bf16.bf16.f32 "
        "{%0,%1,%2,%3}, {%4,%5,%6,%7}, {%8,%9}, {%0,%1,%2,%3};"
        : "+f"(c[0]), "+f"(c[1]), "+f"(c[2]), "+f"(c[3])
        : "r"(a[0]), "r"(a[1]), "r"(a[2]), "r"(a[3]), "r"(b0), "r"(b1));
}
// split (x, y) -> hi bf16x2 (x in low half) and lo bf16x2 (residual)
__device__ __forceinline__ void split2(float x, float y, uint32_t& h, uint32_t& l) {
    asm("cvt.rn.bf16x2.f32 %0, %1, %2;" : "=r"(h) : "f"(y), "f"(x));
    float fx = __uint_as_float(h << 16);
    float fy = __uint_as_float(h & 0xffff0000u);
    float lx = x - fx, ly = y - fy;
    asm("cvt.rn.bf16x2.f32 %0, %1, %2;" : "=r"(l) : "f"(ly), "f"(lx));
}

// ---------------- GEMM mainloop ----------------
// C[128,128] += sum over segments of A_seg[128, kdim] * B_seg[128, kdim]^T
// A, B row-major, K contiguous. Double-buffered smem; smem stores bf16 hi/lo pairs
// pre-arranged in mma.m16n8k16 fragment order so consumers use plain LDS.128.
//
// A region per term: 8 mtiles x 2 ktiles blocks of 128 b32 (lane*4 + r).
// B region per term: 16 ntiles blocks of 128 b32 ((g*4+t)*4 + kt*2 + r) — one
// LDS.128 per lane yields the b-frags for BOTH k-steps.
template <int CPS>   // chunks per segment (kdim / KC)
__device__ __forceinline__ void run_gemm(uint32_t* smp, uint32_t smb,
                                         const float* A0, const float* A1, const float* A2,
                                         const float* B0, const float* B1, const float* B2,
                                         int nseg, const int kdim, float (&acc)[4][4][4]) {
    const int tid  = threadIdx.x;
    const int lane = tid & 31;
    const int wid  = tid >> 5;
    const int wm   = wid >> 2;      // 0..1
    const int wn   = wid & 3;       // 0..3
    const int rbase = tid >> 4;     // 0..15
    const int pc    = tid & 15;     // float2 pair column within KC
    const int kt_p  = pc >> 3, kk = pc & 7, tt = kk & 3, kh = kk >> 2;

    int aslot[8], bslot[8];
    long long goff[8];
#pragma unroll
    for (int i = 0; i < 8; ++i) {
        const int row = rbase + 16 * i;
        const int mt = row >> 4, rm = row & 15, g = rm & 7, rh = rm >> 3;
        aslot[i] = ((mt * 2 + kt_p) << 7) + ((g * 4 + tt) << 2) + (rh + 2 * kh);
        const int nt = row >> 3, gn = row & 7;
        bslot[i] = (nt << 7) + ((gn * 4 + tt) << 2) + kt_p * 2 + kh;
        goff[i] = (long long)row * kdim + 2 * pc;
    }

    const int NC = nseg * CPS;
    float2 av[8], bv[8];
#pragma unroll
    for (int i = 0; i < 8; ++i) {
        av[i] = *(const float2*)(A0 + goff[i]);
        bv[i] = *(const float2*)(B0 + goff[i]);
    }

    for (int c = 0; c < NC; ++c) {
        const int s = c & 1;
        uint32_t* st = smp + s * STAGE_B32;
#pragma unroll
        for (int i = 0; i < 8; ++i) {
            uint32_t h, l;
            split2(av[i].x, av[i].y, h, l);
            st[aslot[i]]        = h;
            st[2048 + aslot[i]] = l;
            split2(bv[i].x, bv[i].y, h, l);
            st[4096 + bslot[i]] = h;
            st[6144 + bslot[i]] = l;
        }
        if (c + 1 < NC) {
            const int cn = c + 1;
            const int seg = cn / CPS, kc = cn % CPS;
            const float* An = (seg == 0) ? A0 : ((seg == 1) ? A1 : A2);
            const float* Bn = (seg == 0) ? B0 : ((seg == 1) ? B1 : B2);
            An += (long long)kc * KC;
            Bn += (long long)kc * KC;
#pragma unroll
            for (int i = 0; i < 8; ++i) {
                av[i] = *(const float2*)(An + goff[i]);
                bv[i] = *(const float2*)(Bn + goff[i]);
            }
        }
        __syncthreads();

        const uint32_t base = smb + s * (STAGE_B32 * 4);
        uint32_t bh[4][4], bl[4][4];
#pragma unroll
        for (int n = 0; n < 4; ++n) {
            const uint32_t boff = ((wn * 4 + n) << 9) + lane * 16;
            lds128(bh[n], base + 16384 + boff);
            lds128(bl[n], base + 24576 + boff);
        }
#pragma unroll
        for (int kt = 0; kt < 2; ++kt) {
#pragma unroll
            for (int m = 0; m < 4; ++m) {
                uint32_t ah[4], al[4];
                const uint32_t aoff = ((((wm * 4 + m) * 2) + kt) << 9) + lane * 16;
                lds128(ah, base + aoff);
                lds128(al, base + 8192 + aoff);
#pragma unroll
                for (int n = 0; n < 4; ++n) {
                    const uint32_t b0h = bh[n][kt * 2], b1h = bh[n][kt * 2 + 1];
                    const uint32_t b0l = bl[n][kt * 2], b1l = bl[n][kt * 2 + 1];
                    mma16816(acc[m][n], ah, b0h, b1h);
                    mma16816(acc[m][n], ah, b0l, b1l);
                    mma16816(acc[m][n], al, b0h, b1h);
                }
            }
        }
    }
}

// ---------------- encoder ----------------
__global__ __launch_bounds__(256) void encoder_mma(const float* __restrict__ resid,  // [L,B,D]
                                                   const float* __restrict__ enc_w,  // [L,F,D]
                                                   const float* __restrict__ enc_b,  // [L,F]
                                                   float* __restrict__ out) {
    extern __shared__ uint32_t smraw[];
    __shared__ float sbias[128];
    __shared__ float s_sp[8];
    __shared__ int   s_cnt[8];

    const int tid = threadIdx.x;
    const int l   = blockIdx.z;
    const int m0  = blockIdx.y * 128;
    const int n0  = blockIdx.x * 128;

    if (tid < 128) sbias[tid] = enc_b[(long long)l * FNUM + n0 + tid];

    float acc[4][4][4];
#pragma unroll
    for (int m = 0; m < 4; ++m)
#pragma unroll
        for (int n = 0; n < 4; ++n)
#pragma unroll
            for (int q = 0; q < 4; ++q) acc[m][n][q] = 0.0f;

    const float* A = resid + ((long long)l * BNUM + m0) * DNUM;
    const float* W = enc_w + ((long long)l * FNUM + n0) * DNUM;
    run_gemm<DNUM / KC>(smraw, smem_u32(smraw), A, A, A, W, W, W, 1, DNUM, acc);

    const int lane = tid & 31, wid = tid >> 5;
    const int wm = wid >> 2, wn = wid & 3;
    const int g = lane >> 2, tt = lane & 3;

    float sp = 0.0f;
    int   cnt = 0;
#pragma unroll
    for (int m = 0; m < 4; ++m) {
        const int r0 = m0 + wm * 64 + m * 16 + g;
#pragma unroll
        for (int n = 0; n < 4; ++n) {
            const int cl  = wn * 32 + n * 8 + tt * 2;
            const float b0 = sbias[cl], b1 = sbias[cl + 1];
            float x0 = fmaxf(acc[m][n][0] + b0, 0.0f);
            float x1 = fmaxf(acc[m][n][1] + b1, 0.0f);
            float x2 = fmaxf(acc[m][n][2] + b0, 0.0f);
            float x3 = fmaxf(acc[m][n][3] + b1, 0.0f);
            sp  += (x0 + x1) + (x2 + x3);
            cnt += (x0 > 0.0f) + (x1 > 0.0f) + (x2 > 0.0f) + (x3 > 0.0f);
            float* p0 = out + FEATS_OFF + ((long long)l * BNUM + r0) * FNUM + n0 + cl;
            float* p1 = out + FEATS_OFF + ((long long)l * BNUM + r0 + 8) * FNUM + n0 + cl;
            *(float2*)p0 = make_float2(x0, x1);
            *(float2*)p1 = make_float2(x2, x3);
        }
    }
#pragma unroll
    for (int o = 16; o > 0; o >>= 1) {
        sp  += __shfl_down_sync(0xffffffffu, sp, o);
        cnt += __shfl_down_sync(0xffffffffu, cnt, o);
    }
    if (lane == 0) { s_sp[wid] = sp; s_cnt[wid] = cnt; }
    __syncthreads();
    if (tid == 0) {
        float tsp = 0.0f; int tc = 0;
        for (int w = 0; w < 8; ++w) { tsp += s_sp[w]; tc += s_cnt[w]; }
        atomicAdd(&g_sp_sum, (double)tsp);
        atomicAdd(&g_cnt[l], (unsigned long long)tc);
    }
}

// ---------------- decoder ----------------
__global__ __launch_bounds__(256) void decoder_mma(const float* __restrict__ feats,  // [L,B,F]
                                                   const float* __restrict__ dec_w,  // [P,D,F]
                                                   const float* __restrict__ tgt,    // [L,B,D]
                                                   float* __restrict__ out) {
    extern __shared__ uint32_t smraw[];
    __shared__ float s_sq[8];

    const int tid = threadIdx.x;
    const int t   = blockIdx.z;
    const int m0  = blockIdx.y * 128;
    const int n0  = blockIdx.x * 128;

    float acc[4][4][4];
#pragma unroll
    for (int m = 0; m < 4; ++m)
#pragma unroll
        for (int n = 0; n < 4; ++n)
#pragma unroll
            for (int q = 0; q < 4; ++q) acc[m][n][q] = 0.0f;

    const int s_lo = (t >= 2) ? (t - 2) : 0;
    const int nseg = t - s_lo + 1;
    const float* As[3]; const float* Bs[3];
#pragma unroll
    for (int i = 0; i < 3; ++i) {
        const int s    = (s_lo + i <= t) ? (s_lo + i) : t;
        const int base = (s <= 5) ? (3 * s) : (2 * s + 6);
        const int p    = base + (t - s);
        As[i] = feats + ((long long)s * BNUM + m0) * FNUM;
        Bs[i] = dec_w + ((long long)p * DNUM + n0) * FNUM;
    }
    run_gemm<FNUM / KC>(smraw, smem_u32(smraw), As[0], As[1], As[2],
                        Bs[0], Bs[1], Bs[2], nseg, FNUM, acc);

    const int lane = tid & 31, wid = tid >> 5;
    const int wm = wid >> 2, wn = wid & 3;
    const int g = lane >> 2, tt = lane & 3;

    float sq = 0.0f;
#pragma unroll
    for (int m = 0; m < 4; ++m) {
        const int r0 = m0 + wm * 64 + m * 16 + g;
#pragma unroll
        for (int n = 0; n < 4; ++n) {
            const int col = n0 + wn * 32 + n * 8 + tt * 2;
            const long long row0 = (long long)t * BNUM + r0;
            const long long row1 = row0 + 8;
            float2 t0 = *(const float2*)(tgt + row0 * DNUM + col);
            float2 t1 = *(const float2*)(tgt + row1 * DNUM + col);
            const float v0 = acc[m][n][0], v1 = acc[m][n][1];
            const float v2 = acc[m][n][2], v3 = acc[m][n][3];
            float d0 = v0 - t0.x, d1 = v1 - t0.y, d2 = v2 - t1.x, d3 = v3 - t1.y;
            sq = fmaf(d0, d0, sq); sq = fmaf(d1, d1, sq);
            sq = fmaf(d2, d2, sq); sq = fmaf(d3, d3, sq);
            *(float2*)(out + row0 * DNUM + col) = make_float2(v0, v1);
            *(float2*)(out + row1 * DNUM + col) = make_float2(v2, v3);
        }
    }
#pragma unroll
    for (int o = 16; o > 0; o >>= 1) sq += __shfl_down_sync(0xffffffffu, sq, o);
    if (lane == 0) s_sq[wid] = sq;
    __syncthreads();
    if (tid == 0) {
        float tsq = 0.0f;
        for (int w = 0; w < 8; ++w) tsq += s_sq[w];
        atomicAdd(&g_sq_sum, (double)tsq);
    }
}

// ---------------- finalize scalars ----------------
__global__ void finalize_kernel(float* __restrict__ out) {
    const int tid = threadIdx.x;
    if (tid == 0) {
        double rl = g_sq_sum / ((double)LNUM * (double)BNUM * (double)DNUM);
        double sl = 1e-4 * (g_sp_sum / ((double)LNUM * (double)BNUM * (double)FNUM));
        out[LOSS_OFF + 0] = (float)(rl + sl);
        out[LOSS_OFF + 1] = (float)rl;
        out[LOSS_OFF + 2] = (float)sl;
    }
    if (tid < LNUM) out[LOSS_OFF + 3 + tid] = (float)((double)g_cnt[tid] / (double)BNUM);
}

// ---------------- entry point ----------------
extern "C" void kernel_launch(void* const* d_in, const int* in_sizes, int n_in,
                              void* d_out, int out_size) {
    (void)in_sizes; (void)n_in; (void)out_size;
    const float* resid   = (const float*)d_in[0];
    const float* targets = (const float*)d_in[1];
    const float* enc_w   = (const float*)d_in[2];
    const float* enc_b   = (const float*)d_in[3];
    const float* dec_w   = (const float*)d_in[4];
    float* out = (float*)d_out;

    static bool attr_done = false;
    if (!attr_done) {
        cudaFuncSetAttribute(encoder_mma, cudaFuncAttributeMaxDynamicSharedMemorySize, SMEM_DYN);
        cudaFuncSetAttribute(decoder_mma, cudaFuncAttributeMaxDynamicSharedMemorySize, SMEM_DYN);
        attr_done = true;
    }

    init_acc_kernel<<<1, 1>>>();

    dim3 genc(FNUM / 128, BNUM / 128, LNUM);  // (64, 8, 8)
    encoder_mma<<<genc, 256, SMEM_DYN>>>(resid, enc_w, enc_b, out);

    dim3 gdec(DNUM / 128, BNUM / 128, LNUM);  // (8, 8, 8)
    decoder_mma<<<gdec, 256, SMEM_DYN>>>(out + FEATS_OFF, dec_w, targets, out);

    finalize_kernel<<<1, 32>>>(out);
}

// round 4
// speedup vs baseline: 2.2759x; 1.0037x over previous
#include <cuda_runtime.h>
#include <cuda_fp16.h>
#include <cstdint>

// ---------------- problem constants ----------------
#define LNUM 8
#define BNUM 1024
#define DNUM 1024
#define FNUM 8192
#define KC   32              // fp32 K elements per chunk
#define STAGE_B32 8192       // 32KB per stage (Ah 8K | Al 8K | Bh 8K | Bl 8K)
#define SMEM_DYN  65536      // 2 stages

static const long long FEATS_OFF = (long long)LNUM * BNUM * DNUM;               // 8388608
static const long long LOSS_OFF  = FEATS_OFF + (long long)LNUM * BNUM * FNUM;   // 75497472

// ---------------- global accumulators ----------------
__device__ double g_sp_sum;
__device__ double g_sq_sum;
__device__ unsigned long long g_cnt[LNUM];

__global__ void init_acc_kernel() {
    g_sp_sum = 0.0;
    g_sq_sum = 0.0;
    for (int i = 0; i < LNUM; ++i) g_cnt[i] = 0ull;
}

// ---------------- small helpers ----------------
__device__ __forceinline__ uint32_t smem_u32(const void* p) {
    uint32_t a;
    asm("{ .reg .u64 t; cvta.to.shared.u64 t, %1; cvt.u32.u64 %0, t; }" : "=r"(a) : "l"(p));
    return a;
}
__device__ __forceinline__ void lds128(uint32_t (&r)[4], uint32_t addr) {
    asm volatile("ld.shared.v4.b32 {%0,%1,%2,%3}, [%4];"
        : "=r"(r[0]), "=r"(r[1]), "=r"(r[2]), "=r"(r[3]) : "r"(addr));
}
__device__ __forceinline__ void mma16816(float (&c)[4], const uint32_t (&a)[4],
                                         uint32_t b0, uint32_t b1) {
    asm volatile("mma.sync.aligned.m16n8k16.row.col.f32.f16.f16.f32 "
        "{%0,%1,%2,%3}, {%4,%5,%6,%7}, {%8,%9}, {%0,%1,%2,%3};"
        : "+f"(c[0]), "+f"(c[1]), "+f"(c[2]), "+f"(c[3])
        : "r"(a[0]), "r"(a[1]), "r"(a[2]), "r"(a[3]), "r"(b0), "r"(b1));
}
// split (x, y) -> hi f16x2 (x in low half) and lo f16x2 (residual)
__device__ __forceinline__ void split2(float x, float y, uint32_t& h, uint32_t& l) {
    asm("cvt.rn.f16x2.f32 %0, %1, %2;" : "=r"(h) : "f"(y), "f"(x));
    float fx, fy;
    asm("{ .reg .f16 a, b; mov.b32 {a, b}, %2; cvt.f32.f16 %0, a; cvt.f32.f16 %1, b; }"
        : "=f"(fx), "=f"(fy) : "r"(h));
    float lx = x - fx, ly = y - fy;
    asm("cvt.rn.f16x2.f32 %0, %1, %2;" : "=r"(l) : "f"(ly), "f"(lx));
}

// ---------------- GEMM mainloop ----------------
// C[128,128] += sum over segments of A_seg[128, kdim] * B_seg[128, kdim]^T
// A, B row-major, K contiguous. Double-buffered smem; smem stores fp16 hi/lo pairs
// pre-arranged in mma.m16n8k16 fragment order so consumers use plain LDS.128.
// Consumer issues the 3 split terms TERM-OUTERMOST: consecutive mmas touch 16
// distinct accumulators (reuse distance 16) -> no accumulator RAW stalls.
template <int CPS>   // chunks per segment (kdim / KC)
__device__ __forceinline__ void run_gemm(uint32_t* smp, uint32_t smb,
                                         const float* A0, const float* A1, const float* A2,
                                         const float* B0, const float* B1, const float* B2,
                                         int nseg, const int kdim, float (&acc)[4][4][4]) {
    const int tid  = threadIdx.x;
    const int lane = tid & 31;
    const int wid  = tid >> 5;
    const int wm   = wid >> 2;      // 0..1
    const int wn   = wid & 3;       // 0..3
    const int rbase = tid >> 4;     // 0..15
    const int pc    = tid & 15;     // float2 pair column within KC
    const int kt_p  = pc >> 3, kk = pc & 7, tt = kk & 3, kh = kk >> 2;

    int aslot[8], bslot[8];
    long long goff[8];
#pragma unroll
    for (int i = 0; i < 8; ++i) {
        const int row = rbase + 16 * i;
        const int mt = row >> 4, rm = row & 15, g = rm & 7, rh = rm >> 3;
        aslot[i] = ((mt * 2 + kt_p) << 7) + ((g * 4 + tt) << 2) + (rh + 2 * kh);
        const int nt = row >> 3, gn = row & 7;
        bslot[i] = (nt << 7) + ((gn * 4 + tt) << 2) + kt_p * 2 + kh;
        goff[i] = (long long)row * kdim + 2 * pc;
    }

    const int NC = nseg * CPS;
    float2 av[8], bv[8];
#pragma unroll
    for (int i = 0; i < 8; ++i) {
        av[i] = *(const float2*)(A0 + goff[i]);
        bv[i] = *(const float2*)(B0 + goff[i]);
    }

    for (int c = 0; c < NC; ++c) {
        const int s = c & 1;
        uint32_t* st = smp + s * STAGE_B32;
#pragma unroll
        for (int i = 0; i < 8; ++i) {
            uint32_t h, l;
            split2(av[i].x, av[i].y, h, l);
            st[aslot[i]]        = h;
            st[2048 + aslot[i]] = l;
            split2(bv[i].x, bv[i].y, h, l);
            st[4096 + bslot[i]] = h;
            st[6144 + bslot[i]] = l;
        }
        if (c + 1 < NC) {
            const int cn = c + 1;
            const int seg = cn / CPS, kc = cn % CPS;
            const float* An = (seg == 0) ? A0 : ((seg == 1) ? A1 : A2);
            const float* Bn = (seg == 0) ? B0 : ((seg == 1) ? B1 : B2);
            An += (long long)kc * KC;
            Bn += (long long)kc * KC;
#pragma unroll
            for (int i = 0; i < 8; ++i) {
                av[i] = *(const float2*)(An + goff[i]);
                bv[i] = *(const float2*)(Bn + goff[i]);
            }
        }
        __syncthreads();

        const uint32_t base = smb + s * (STAGE_B32 * 4);
        uint32_t bh[4][4], bl[4][4];
#pragma unroll
        for (int n = 0; n < 4; ++n) {
            const uint32_t boff = ((wn * 4 + n) << 9) + lane * 16;
            lds128(bh[n], base + 16384 + boff);
            lds128(bl[n], base + 24576 + boff);
        }
#pragma unroll
        for (int kt = 0; kt < 2; ++kt) {
            uint32_t ah[4][4], al[4][4];
#pragma unroll
            for (int m = 0; m < 4; ++m) {
                const uint32_t aoff = ((((wm * 4 + m) * 2) + kt) << 9) + lane * 16;
                lds128(ah[m], base + aoff);
                lds128(al[m], base + 8192 + aoff);
            }
            // term hh: 16 independent accumulators back-to-back
#pragma unroll
            for (int m = 0; m < 4; ++m)
#pragma unroll
                for (int n = 0; n < 4; ++n)
                    mma16816(acc[m][n], ah[m], bh[n][kt * 2], bh[n][kt * 2 + 1]);
            // term hl
#pragma unroll
            for (int m = 0; m < 4; ++m)
#pragma unroll
                for (int n = 0; n < 4; ++n)
                    mma16816(acc[m][n], ah[m], bl[n][kt * 2], bl[n][kt * 2 + 1]);
            // term lh
#pragma unroll
            for (int m = 0; m < 4; ++m)
#pragma unroll
                for (int n = 0; n < 4; ++n)
                    mma16816(acc[m][n], al[m], bh[n][kt * 2], bh[n][kt * 2 + 1]);
        }
    }
}

// ---------------- encoder ----------------
__global__ __launch_bounds__(256) void encoder_mma(const float* __restrict__ resid,  // [L,B,D]
                                                   const float* __restrict__ enc_w,  // [L,F,D]
                                                   const float* __restrict__ enc_b,  // [L,F]
                                                   float* __restrict__ out) {
    extern __shared__ uint32_t smraw[];
    __shared__ float sbias[128];
    __shared__ float s_sp[8];
    __shared__ int   s_cnt[8];

    const int tid = threadIdx.x;
    const int l   = blockIdx.z;
    const int m0  = blockIdx.y * 128;
    const int n0  = blockIdx.x * 128;

    if (tid < 128) sbias[tid] = enc_b[(long long)l * FNUM + n0 + tid];

    float acc[4][4][4];
#pragma unroll
    for (int m = 0; m < 4; ++m)
#pragma unroll
        for (int n = 0; n < 4; ++n)
#pragma unroll
            for (int q = 0; q < 4; ++q) acc[m][n][q] = 0.0f;

    const float* A = resid + ((long long)l * BNUM + m0) * DNUM;
    const float* W = enc_w + ((long long)l * FNUM + n0) * DNUM;
    run_gemm<DNUM / KC>(smraw, smem_u32(smraw), A, A, A, W, W, W, 1, DNUM, acc);

    const int lane = tid & 31, wid = tid >> 5;
    const int wm = wid >> 2, wn = wid & 3;
    const int g = lane >> 2, tt = lane & 3;

    float sp = 0.0f;
    int   cnt = 0;
#pragma unroll
    for (int m = 0; m < 4; ++m) {
        const int r0 = m0 + wm * 64 + m * 16 + g;
#pragma unroll
        for (int n = 0; n < 4; ++n) {
            const int cl  = wn * 32 + n * 8 + tt * 2;
            const float b0 = sbias[cl], b1 = sbias[cl + 1];
            float x0 = fmaxf(acc[m][n][0] + b0, 0.0f);
            float x1 = fmaxf(acc[m][n][1] + b1, 0.0f);
            float x2 = fmaxf(acc[m][n][2] + b0, 0.0f);
            float x3 = fmaxf(acc[m][n][3] + b1, 0.0f);
            sp  += (x0 + x1) + (x2 + x3);
            cnt += (x0 > 0.0f) + (x1 > 0.0f) + (x2 > 0.0f) + (x3 > 0.0f);
            float* p0 = out + FEATS_OFF + ((long long)l * BNUM + r0) * FNUM + n0 + cl;
            float* p1 = out + FEATS_OFF + ((long long)l * BNUM + r0 + 8) * FNUM + n0 + cl;
            *(float2*)p0 = make_float2(x0, x1);
            *(float2*)p1 = make_float2(x2, x3);
        }
    }
#pragma unroll
    for (int o = 16; o > 0; o >>= 1) {
        sp  += __shfl_down_sync(0xffffffffu, sp, o);
        cnt += __shfl_down_sync(0xffffffffu, cnt, o);
    }
    if (lane == 0) { s_sp[wid] = sp; s_cnt[wid] = cnt; }
    __syncthreads();
    if (tid == 0) {
        float tsp = 0.0f; int tc = 0;
        for (int w = 0; w < 8; ++w) { tsp += s_sp[w]; tc += s_cnt[w]; }
        atomicAdd(&g_sp_sum, (double)tsp);
        atomicAdd(&g_cnt[l], (unsigned long long)tc);
    }
}

// ---------------- decoder ----------------
__global__ __launch_bounds__(256) void decoder_mma(const float* __restrict__ feats,  // [L,B,F]
                                                   const float* __restrict__ dec_w,  // [P,D,F]
                                                   const float* __restrict__ tgt,    // [L,B,D]
                                                   float* __restrict__ out) {
    extern __shared__ uint32_t smraw[];
    __shared__ float s_sq[8];

    const int tid = threadIdx.x;
    const int t   = blockIdx.z;
    const int m0  = blockIdx.y * 128;
    const int n0  = blockIdx.x * 128;

    float acc[4][4][4];
#pragma unroll
    for (int m = 0; m < 4; ++m)
#pragma unroll
        for (int n = 0; n < 4; ++n)
#pragma unroll
            for (int q = 0; q < 4; ++q) acc[m][n][q] = 0.0f;

    const int s_lo = (t >= 2) ? (t - 2) : 0;
    const int nseg = t - s_lo + 1;
    const float* As[3]; const float* Bs[3];
#pragma unroll
    for (int i = 0; i < 3; ++i) {
        const int s    = (s_lo + i <= t) ? (s_lo + i) : t;
        const int base = (s <= 5) ? (3 * s) : (2 * s + 6);
        const int p    = base + (t - s);
        As[i] = feats + ((long long)s * BNUM + m0) * FNUM;
        Bs[i] = dec_w + ((long long)p * DNUM + n0) * FNUM;
    }
    run_gemm<FNUM / KC>(smraw, smem_u32(smraw), As[0], As[1], As[2],
                        Bs[0], Bs[1], Bs[2], nseg, FNUM, acc);

    const int lane = tid & 31, wid = tid >> 5;
    const int wm = wid >> 2, wn = wid & 3;
    const int g = lane >> 2, tt = lane & 3;

    float sq = 0.0f;
#pragma unroll
    for (int m = 0; m < 4; ++m) {
        const int r0 = m0 + wm * 64 + m * 16 + g;
#pragma unroll
        for (int n = 0; n < 4; ++n) {
            const int col = n0 + wn * 32 + n * 8 + tt * 2;
            const long long row0 = (long long)t * BNUM + r0;
            const long long row1 = row0 + 8;
            float2 t0 = *(const float2*)(tgt + row0 * DNUM + col);
            float2 t1 = *(const float2*)(tgt + row1 * DNUM + col);
            const float v0 = acc[m][n][0], v1 = acc[m][n][1];
            const float v2 = acc[m][n][2], v3 = acc[m][n][3];
            float d0 = v0 - t0.x, d1 = v1 - t0.y, d2 = v2 - t1.x, d3 = v3 - t1.y;
            sq = fmaf(d0, d0, sq); sq = fmaf(d1, d1, sq);
            sq = fmaf(d2, d2, sq); sq = fmaf(d3, d3, sq);
            *(float2*)(out + row0 * DNUM + col) = make_float2(v0, v1);
            *(float2*)(out + row1 * DNUM + col) = make_float2(v2, v3);
        }
    }
#pragma unroll
    for (int o = 16; o > 0; o >>= 1) sq += __shfl_down_sync(0xffffffffu, sq, o);
    if (lane == 0) s_sq[wid] = sq;
    __syncthreads();
    if (tid == 0) {
        float tsq = 0.0f;
        for (int w = 0; w < 8; ++w) tsq += s_sq[w];
        atomicAdd(&g_sq_sum, (double)tsq);
    }
}

// ---------------- finalize scalars ----------------
__global__ void finalize_kernel(float* __restrict__ out) {
    const int tid = threadIdx.x;
    if (tid == 0) {
        double rl = g_sq_sum / ((double)LNUM * (double)BNUM * (double)DNUM);
        double sl = 1e-4 * (g_sp_sum / ((double)LNUM * (double)BNUM * (double)FNUM));
        out[LOSS_OFF + 0] = (float)(rl + sl);
        out[LOSS_OFF + 1] = (float)rl;
        out[LOSS_OFF + 2] = (float)sl;
    }
    if (tid < LNUM) out[LOSS_OFF + 3 + tid] = (float)((double)g_cnt[tid] / (double)BNUM);
}

// ---------------- entry point ----------------
extern "C" void kernel_launch(void* const* d_in, const int* in_sizes, int n_in,
                              void* d_out, int out_size) {
    (void)in_sizes; (void)n_in; (void)out_size;
    const float* resid   = (const float*)d_in[0];
    const float* targets = (const float*)d_in[1];
    const float* enc_w   = (const float*)d_in[2];
    const float* enc_b   = (const float*)d_in[3];
    const float* dec_w   = (const float*)d_in[4];
    float* out = (float*)d_out;

    static bool attr_done = false;
    if (!attr_done) {
        cudaFuncSetAttribute(encoder_mma, cudaFuncAttributeMaxDynamicSharedMemorySize, SMEM_DYN);
        cudaFuncSetAttribute(decoder_mma, cudaFuncAttributeMaxDynamicSharedMemorySize, SMEM_DYN);
        attr_done = true;
    }

    init_acc_kernel<<<1, 1>>>();

    dim3 genc(FNUM / 128, BNUM / 128, LNUM);  // (64, 8, 8)
    encoder_mma<<<genc, 256, SMEM_DYN>>>(resid, enc_w, enc_b, out);

    dim3 gdec(DNUM / 128, BNUM / 128, LNUM);  // (8, 8, 8)
    decoder_mma<<<gdec, 256, SMEM_DYN>>>(out + FEATS_OFF, dec_w, targets, out);

    finalize_kernel<<<1, 32>>>(out);
}

// round 5
// speedup vs baseline: 2.9577x; 1.2996x over previous
#include <cuda_runtime.h>
#include <cuda_fp16.h>
#include <cstdint>

// ---------------- problem constants ----------------
#define LNUM 8
#define BNUM 1024
#define DNUM 1024
#define FNUM 8192
#define KC   32              // fp32 K elements per chunk

static const long long FEATS_OFF = (long long)LNUM * BNUM * DNUM;               // 8388608
static const long long LOSS_OFF  = FEATS_OFF + (long long)LNUM * BNUM * FNUM;   // 75497472

// ---------------- global accumulators ----------------
__device__ double g_sp_sum;
__device__ double g_sq_sum;
__device__ unsigned long long g_cnt[LNUM];

__global__ void init_acc_kernel() {
    g_sp_sum = 0.0;
    g_sq_sum = 0.0;
    for (int i = 0; i < LNUM; ++i) g_cnt[i] = 0ull;
}

// ---------------- small helpers ----------------
__device__ __forceinline__ uint32_t smem_u32(const void* p) {
    uint32_t a;
    asm("{ .reg .u64 t; cvta.to.shared.u64 t, %1; cvt.u32.u64 %0, t; }" : "=r"(a) : "l"(p));
    return a;
}
__device__ __forceinline__ void lds128(uint32_t (&r)[4], uint32_t addr) {
    asm volatile("ld.shared.v4.b32 {%0,%1,%2,%3}, [%4];"
        : "=r"(r[0]), "=r"(r[1]), "=r"(r[2]), "=r"(r[3]) : "r"(addr));
}
__device__ __forceinline__ void mma16816(float (&c)[4], const uint32_t (&a)[4],
                                         uint32_t b0, uint32_t b1) {
    asm volatile("mma.sync.aligned.m16n8k16.row.col.f32.f16.f16.f32 "
        "{%0,%1,%2,%3}, {%4,%5,%6,%7}, {%8,%9}, {%0,%1,%2,%3};"
        : "+f"(c[0]), "+f"(c[1]), "+f"(c[2]), "+f"(c[3])
        : "r"(a[0]), "r"(a[1]), "r"(a[2]), "r"(a[3]), "r"(b0), "r"(b1));
}
// split (x, y) -> hi f16x2 (x in low half) and lo f16x2 (residual)
__device__ __forceinline__ void split2(float x, float y, uint32_t& h, uint32_t& l) {
    asm("cvt.rn.f16x2.f32 %0, %1, %2;" : "=r"(h) : "f"(y), "f"(x));
    float fx, fy;
    asm("{ .reg .f16 a, b; mov.b32 {a, b}, %2; cvt.f32.f16 %0, a; cvt.f32.f16 %1, b; }"
        : "=f"(fx), "=f"(fy) : "r"(h));
    float lx = x - fx, ly = y - fy;
    asm("cvt.rn.f16x2.f32 %0, %1, %2;" : "=r"(l) : "f"(ly), "f"(lx));
}

// ---------------- GEMM mainloop ----------------
// C[128,128] += sum over segments of A_seg[128, kdim] * B_seg[128, kdim]^T
// fp16 hi/lo split, TERMS = 3 (hh + hl + lh) or 2 (hh + hl; A lo dropped).
// smem stores fp16x2 words pre-arranged in mma.m16n8k16 fragment order so
// consumers use plain conflict-free LDS.128. Double-buffered stages.
template <int CPS, int TERMS>   // CPS = chunks per segment (kdim / KC)
__device__ __forceinline__ void run_gemm(uint32_t* smp, uint32_t smb,
                                         const float* A0, const float* A1, const float* A2,
                                         const float* B0, const float* B1, const float* B2,
                                         int nseg, const int kdim, float (&acc)[4][4][4]) {
    constexpr int AH = 0;
    constexpr int AL = 2048;                        // only used when TERMS == 3
    constexpr int BH = (TERMS == 3) ? 4096 : 2048;
    constexpr int BL = BH + 2048;
    constexpr int STW = (TERMS == 3) ? 8192 : 6144; // stage words

    const int tid  = threadIdx.x;
    const int lane = tid & 31;
    const int wid  = tid >> 5;
    const int wm   = wid >> 2;      // 0..1
    const int wn   = wid & 3;       // 0..3
    const int rbase = tid >> 4;     // 0..15
    const int pc    = tid & 15;     // float2 pair column within KC
    const int kt_p  = pc >> 3, kk = pc & 7, tt = kk & 3, kh = kk >> 2;

    int aslot[8], bslot[8];
    long long goff[8];
#pragma unroll
    for (int i = 0; i < 8; ++i) {
        const int row = rbase + 16 * i;
        const int mt = row >> 4, rm = row & 15, g = rm & 7, rh = rm >> 3;
        aslot[i] = ((mt * 2 + kt_p) << 7) + ((g * 4 + tt) << 2) + (rh + 2 * kh);
        const int nt = row >> 3, gn = row & 7;
        bslot[i] = (nt << 7) + ((gn * 4 + tt) << 2) + kt_p * 2 + kh;
        goff[i] = (long long)row * kdim + 2 * pc;
    }

    const int NC = nseg * CPS;
    float2 av[8], bv[8];
#pragma unroll
    for (int i = 0; i < 8; ++i) {
        av[i] = *(const float2*)(A0 + goff[i]);
        bv[i] = *(const float2*)(B0 + goff[i]);
    }

    for (int c = 0; c < NC; ++c) {
        const int s = c & 1;
        uint32_t* st = smp + s * STW;
#pragma unroll
        for (int i = 0; i < 8; ++i) {
            uint32_t h, l;
            split2(av[i].x, av[i].y, h, l);
            st[AH + aslot[i]] = h;
            if (TERMS == 3) st[AL + aslot[i]] = l;
            split2(bv[i].x, bv[i].y, h, l);
            st[BH + bslot[i]] = h;
            st[BL + bslot[i]] = l;
        }
        if (c + 1 < NC) {
            const int cn = c + 1;
            const int seg = cn / CPS, kc = cn % CPS;
            const float* An = (seg == 0) ? A0 : ((seg == 1) ? A1 : A2);
            const float* Bn = (seg == 0) ? B0 : ((seg == 1) ? B1 : B2);
            An += (long long)kc * KC;
            Bn += (long long)kc * KC;
#pragma unroll
            for (int i = 0; i < 8; ++i) {
                av[i] = *(const float2*)(An + goff[i]);
                bv[i] = *(const float2*)(Bn + goff[i]);
            }
        }
        __syncthreads();

        const uint32_t base = smb + s * (STW * 4);
        uint32_t bh[4][4], bl[4][4];
#pragma unroll
        for (int n = 0; n < 4; ++n) {
            const uint32_t boff = ((wn * 4 + n) << 9) + lane * 16;
            lds128(bh[n], base + BH * 4 + boff);
            lds128(bl[n], base + BL * 4 + boff);
        }
#pragma unroll
        for (int kt = 0; kt < 2; ++kt) {
            uint32_t ah[4][4], al[4][4];
#pragma unroll
            for (int m = 0; m < 4; ++m) {
                const uint32_t aoff = ((((wm * 4 + m) * 2) + kt) << 9) + lane * 16;
                lds128(ah[m], base + aoff);
                if (TERMS == 3) lds128(al[m], base + AL * 4 + aoff);
            }
            // term hh
#pragma unroll
            for (int m = 0; m < 4; ++m)
#pragma unroll
                for (int n = 0; n < 4; ++n)
                    mma16816(acc[m][n], ah[m], bh[n][kt * 2], bh[n][kt * 2 + 1]);
            // term hl
#pragma unroll
            for (int m = 0; m < 4; ++m)
#pragma unroll
                for (int n = 0; n < 4; ++n)
                    mma16816(acc[m][n], ah[m], bl[n][kt * 2], bl[n][kt * 2 + 1]);
            // term lh (3-term only)
            if (TERMS == 3) {
#pragma unroll
                for (int m = 0; m < 4; ++m)
#pragma unroll
                    for (int n = 0; n < 4; ++n)
                        mma16816(acc[m][n], al[m], bh[n][kt * 2], bh[n][kt * 2 + 1]);
            }
        }
    }
}

// ---------------- encoder (3-term: feats is a direct output) ----------------
__global__ __launch_bounds__(256) void encoder_mma(const float* __restrict__ resid,  // [L,B,D]
                                                   const float* __restrict__ enc_w,  // [L,F,D]
                                                   const float* __restrict__ enc_b,  // [L,F]
                                                   float* __restrict__ out) {
    extern __shared__ uint32_t smraw[];
    __shared__ float sbias[128];
    __shared__ float s_sp[8];
    __shared__ int   s_cnt[8];

    const int tid = threadIdx.x;
    const int l   = blockIdx.z;
    const int m0  = blockIdx.y * 128;
    const int n0  = blockIdx.x * 128;

    if (tid < 128) sbias[tid] = enc_b[(long long)l * FNUM + n0 + tid];

    float acc[4][4][4];
#pragma unroll
    for (int m = 0; m < 4; ++m)
#pragma unroll
        for (int n = 0; n < 4; ++n)
#pragma unroll
            for (int q = 0; q < 4; ++q) acc[m][n][q] = 0.0f;

    const float* A = resid + ((long long)l * BNUM + m0) * DNUM;
    const float* W = enc_w + ((long long)l * FNUM + n0) * DNUM;
    run_gemm<DNUM / KC, 3>(smraw, smem_u32(smraw), A, A, A, W, W, W, 1, DNUM, acc);

    const int lane = tid & 31, wid = tid >> 5;
    const int wm = wid >> 2, wn = wid & 3;
    const int g = lane >> 2, tt = lane & 3;

    float sp = 0.0f;
    int   cnt = 0;
#pragma unroll
    for (int m = 0; m < 4; ++m) {
        const int r0 = m0 + wm * 64 + m * 16 + g;
#pragma unroll
        for (int n = 0; n < 4; ++n) {
            const int cl  = wn * 32 + n * 8 + tt * 2;
            const float b0 = sbias[cl], b1 = sbias[cl + 1];
            float x0 = fmaxf(acc[m][n][0] + b0, 0.0f);
            float x1 = fmaxf(acc[m][n][1] + b1, 0.0f);
            float x2 = fmaxf(acc[m][n][2] + b0, 0.0f);
            float x3 = fmaxf(acc[m][n][3] + b1, 0.0f);
            sp  += (x0 + x1) + (x2 + x3);
            cnt += (x0 > 0.0f) + (x1 > 0.0f) + (x2 > 0.0f) + (x3 > 0.0f);
            float* p0 = out + FEATS_OFF + ((long long)l * BNUM + r0) * FNUM + n0 + cl;
            float* p1 = out + FEATS_OFF + ((long long)l * BNUM + r0 + 8) * FNUM + n0 + cl;
            *(float2*)p0 = make_float2(x0, x1);
            *(float2*)p1 = make_float2(x2, x3);
        }
    }
#pragma unroll
    for (int o = 16; o > 0; o >>= 1) {
        sp  += __shfl_down_sync(0xffffffffu, sp, o);
        cnt += __shfl_down_sync(0xffffffffu, cnt, o);
    }
    if (lane == 0) { s_sp[wid] = sp; s_cnt[wid] = cnt; }
    __syncthreads();
    if (tid == 0) {
        float tsp = 0.0f; int tc = 0;
        for (int w = 0; w < 8; ++w) { tsp += s_sp[w]; tc += s_cnt[w]; }
        atomicAdd(&g_sp_sum, (double)tsp);
        atomicAdd(&g_cnt[l], (unsigned long long)tc);
    }
}

// ---------------- decoder (2-term; 72% of chunks) ----------------
// 1D grid, t descending so 3-segment CTAs launch first (trim wave tail).
__global__ __launch_bounds__(256) void decoder_mma(const float* __restrict__ feats,  // [L,B,F]
                                                   const float* __restrict__ dec_w,  // [P,D,F]
                                                   const float* __restrict__ tgt,    // [L,B,D]
                                                   float* __restrict__ out) {
    extern __shared__ uint32_t smraw[];
    __shared__ float s_sq[8];

    const int tid = threadIdx.x;
    const int bid = blockIdx.x;
    const int t   = 7 - (bid >> 6);
    const int rem = bid & 63;
    const int m0  = (rem >> 3) * 128;
    const int n0  = (rem & 7) * 128;

    float acc[4][4][4];
#pragma unroll
    for (int m = 0; m < 4; ++m)
#pragma unroll
        for (int n = 0; n < 4; ++n)
#pragma unroll
            for (int q = 0; q < 4; ++q) acc[m][n][q] = 0.0f;

    const int s_lo = (t >= 2) ? (t - 2) : 0;
    const int nseg = t - s_lo + 1;
    const float* As[3]; const float* Bs[3];
#pragma unroll
    for (int i = 0; i < 3; ++i) {
        const int s    = (s_lo + i <= t) ? (s_lo + i) : t;
        const int base = (s <= 5) ? (3 * s) : (2 * s + 6);
        const int p    = base + (t - s);
        As[i] = feats + ((long long)s * BNUM + m0) * FNUM;
        Bs[i] = dec_w + ((long long)p * DNUM + n0) * FNUM;
    }
    run_gemm<FNUM / KC, 2>(smraw, smem_u32(smraw), As[0], As[1], As[2],
                           Bs[0], Bs[1], Bs[2], nseg, FNUM, acc);

    const int lane = tid & 31, wid = tid >> 5;
    const int wm = wid >> 2, wn = wid & 3;
    const int g = lane >> 2, tt = lane & 3;

    float sq = 0.0f;
#pragma unroll
    for (int m = 0; m < 4; ++m) {
        const int r0 = m0 + wm * 64 + m * 16 + g;
#pragma unroll
        for (int n = 0; n < 4; ++n) {
            const int col = n0 + wn * 32 + n * 8 + tt * 2;
            const long long row0 = (long long)t * BNUM + r0;
            const long long row1 = row0 + 8;
            float2 t0 = *(const float2*)(tgt + row0 * DNUM + col);
            float2 t1 = *(const float2*)(tgt + row1 * DNUM + col);
            const float v0 = acc[m][n][0], v1 = acc[m][n][1];
            const float v2 = acc[m][n][2], v3 = acc[m][n][3];
            float d0 = v0 - t0.x, d1 = v1 - t0.y, d2 = v2 - t1.x, d3 = v3 - t1.y;
            sq = fmaf(d0, d0, sq); sq = fmaf(d1, d1, sq);
            sq = fmaf(d2, d2, sq); sq = fmaf(d3, d3, sq);
            *(float2*)(out + row0 * DNUM + col) = make_float2(v0, v1);
            *(float2*)(out + row1 * DNUM + col) = make_float2(v2, v3);
        }
    }
#pragma unroll
    for (int o = 16; o > 0; o >>= 1) sq += __shfl_down_sync(0xffffffffu, sq, o);
    if (lane == 0) s_sq[wid] = sq;
    __syncthreads();
    if (tid == 0) {
        float tsq = 0.0f;
        for (int w = 0; w < 8; ++w) tsq += s_sq[w];
        atomicAdd(&g_sq_sum, (double)tsq);
    }
}

// ---------------- finalize scalars ----------------
__global__ void finalize_kernel(float* __restrict__ out) {
    const int tid = threadIdx.x;
    if (tid == 0) {
        double rl = g_sq_sum / ((double)LNUM * (double)BNUM * (double)DNUM);
        double sl = 1e-4 * (g_sp_sum / ((double)LNUM * (double)BNUM * (double)FNUM));
        out[LOSS_OFF + 0] = (float)(rl + sl);
        out[LOSS_OFF + 1] = (float)rl;
        out[LOSS_OFF + 2] = (float)sl;
    }
    if (tid < LNUM) out[LOSS_OFF + 3 + tid] = (float)((double)g_cnt[tid] / (double)BNUM);
}

// ---------------- entry point ----------------
#define SMEM_ENC (2 * 8192 * 4)   // 64 KB
#define SMEM_DEC (2 * 6144 * 4)   // 48 KB

extern "C" void kernel_launch(void* const* d_in, const int* in_sizes, int n_in,
                              void* d_out, int out_size) {
    (void)in_sizes; (void)n_in; (void)out_size;
    const float* resid   = (const float*)d_in[0];
    const float* targets = (const float*)d_in[1];
    const float* enc_w   = (const float*)d_in[2];
    const float* enc_b   = (const float*)d_in[3];
    const float* dec_w   = (const float*)d_in[4];
    float* out = (float*)d_out;

    static bool attr_done = false;
    if (!attr_done) {
        cudaFuncSetAttribute(encoder_mma, cudaFuncAttributeMaxDynamicSharedMemorySize, SMEM_ENC);
        cudaFuncSetAttribute(decoder_mma, cudaFuncAttributeMaxDynamicSharedMemorySize, SMEM_DEC);
        attr_done = true;
    }

    init_acc_kernel<<<1, 1>>>();

    dim3 genc(FNUM / 128, BNUM / 128, LNUM);  // (64, 8, 8)
    encoder_mma<<<genc, 256, SMEM_ENC>>>(resid, enc_w, enc_b, out);

    decoder_mma<<<512, 256, SMEM_DEC>>>(out + FEATS_OFF, dec_w, targets, out);

    finalize_kernel<<<1, 32>>>(out);
}

// round 8
// speedup vs baseline: 3.2196x; 1.0885x over previous
#include <cuda_runtime.h>
#include <cuda_fp16.h>
#include <cstdint>

// ---------------- problem constants ----------------
#define LNUM 8
#define BNUM 1024
#define DNUM 1024
#define FNUM 8192
#define KC   32              // fp32 K elements per chunk

static const long long FEATS_OFF = (long long)LNUM * BNUM * DNUM;               // 8388608
static const long long LOSS_OFF  = FEATS_OFF + (long long)LNUM * BNUM * FNUM;   // 75497472

// ---------------- global accumulators ----------------
__device__ double g_sp_sum;
__device__ double g_sq_sum;
__device__ unsigned long long g_cnt[LNUM];

__global__ void init_acc_kernel() {
    g_sp_sum = 0.0;
    g_sq_sum = 0.0;
    for (int i = 0; i < LNUM; ++i) g_cnt[i] = 0ull;
}

// ---------------- small helpers ----------------
__device__ __forceinline__ uint32_t smem_u32(const void* p) {
    uint32_t a;
    asm("{ .reg .u64 t; cvta.to.shared.u64 t, %1; cvt.u32.u64 %0, t; }" : "=r"(a) : "l"(p));
    return a;
}
__device__ __forceinline__ void lds128(uint32_t (&r)[4], uint32_t addr) {
    asm volatile("ld.shared.v4.b32 {%0,%1,%2,%3}, [%4];"
        : "=r"(r[0]), "=r"(r[1]), "=r"(r[2]), "=r"(r[3]) : "r"(addr));
}
__device__ __forceinline__ void mma16816(float (&c)[4], const uint32_t (&a)[4],
                                         uint32_t b0, uint32_t b1) {
    asm volatile("mma.sync.aligned.m16n8k16.row.col.f32.f16.f16.f32 "
        "{%0,%1,%2,%3}, {%4,%5,%6,%7}, {%8,%9}, {%0,%1,%2,%3};"
        : "+f"(c[0]), "+f"(c[1]), "+f"(c[2]), "+f"(c[3])
        : "r"(a[0]), "r"(a[1]), "r"(a[2]), "r"(a[3]), "r"(b0), "r"(b1));
}
// split (x, y) -> hi f16x2 (x in low half) and lo f16x2 (residual)
__device__ __forceinline__ void split2(float x, float y, uint32_t& h, uint32_t& l) {
    asm("cvt.rn.f16x2.f32 %0, %1, %2;" : "=r"(h) : "f"(y), "f"(x));
    float fx, fy;
    asm("{ .reg .f16 a, b; mov.b32 {a, b}, %2; cvt.f32.f16 %0, a; cvt.f32.f16 %1, b; }"
        : "=f"(fx), "=f"(fy) : "r"(h));
    float lx = x - fx, ly = y - fy;
    asm("cvt.rn.f16x2.f32 %0, %1, %2;" : "=r"(l) : "f"(ly), "f"(lx));
}

// ---------------- GEMM mainloop (R5-proven) ----------------
// C[128,128] += sum over segments of A_seg[128, kdim] * B_seg[128, kdim]^T
// fp16 hi/lo split, TERMS = 3 (hh + hl + lh) or 2 (hh + hl; A lo dropped).
// smem stores fp16x2 words pre-arranged in mma.m16n8k16 fragment order so
// consumers use plain conflict-free LDS.128. Double-buffered stages.
template <int CPS, int TERMS>   // CPS = chunks per segment (kdim / KC)
__device__ __forceinline__ void run_gemm(uint32_t* smp, uint32_t smb,
                                         const float* A0, const float* A1, const float* A2,
                                         const float* B0, const float* B1, const float* B2,
                                         int nseg, const int kdim, float (&acc)[4][4][4]) {
    constexpr int AH = 0;
    constexpr int AL = 2048;                        // only used when TERMS == 3
    constexpr int BH = (TERMS == 3) ? 4096 : 2048;
    constexpr int BL = BH + 2048;
    constexpr int STW = (TERMS == 3) ? 8192 : 6144; // stage words

    const int tid  = threadIdx.x;
    const int lane = tid & 31;
    const int wid  = tid >> 5;
    const int wm   = wid >> 2;      // 0..1
    const int wn   = wid & 3;       // 0..3
    const int rbase = tid >> 4;     // 0..15
    const int pc    = tid & 15;     // float2 pair column within KC
    const int kt_p  = pc >> 3, kk = pc & 7, tt = kk & 3, kh = kk >> 2;

    int aslot[8], bslot[8];
    long long goff[8];
#pragma unroll
    for (int i = 0; i < 8; ++i) {
        const int row = rbase + 16 * i;
        const int mt = row >> 4, rm = row & 15, g = rm & 7, rh = rm >> 3;
        aslot[i] = ((mt * 2 + kt_p) << 7) + ((g * 4 + tt) << 2) + (rh + 2 * kh);
        const int nt = row >> 3, gn = row & 7;
        bslot[i] = (nt << 7) + ((gn * 4 + tt) << 2) + kt_p * 2 + kh;
        goff[i] = (long long)row * kdim + 2 * pc;
    }

    const int NC = nseg * CPS;
    float2 av[8], bv[8];
#pragma unroll
    for (int i = 0; i < 8; ++i) {
        av[i] = *(const float2*)(A0 + goff[i]);
        bv[i] = *(const float2*)(B0 + goff[i]);
    }

    for (int c = 0; c < NC; ++c) {
        const int s = c & 1;
        uint32_t* st = smp + s * STW;
#pragma unroll
        for (int i = 0; i < 8; ++i) {
            uint32_t h, l;
            split2(av[i].x, av[i].y, h, l);
            st[AH + aslot[i]] = h;
            if (TERMS == 3) st[AL + aslot[i]] = l;
            split2(bv[i].x, bv[i].y, h, l);
            st[BH + bslot[i]] = h;
            st[BL + bslot[i]] = l;
        }
        if (c + 1 < NC) {
            const int cn = c + 1;
            const int seg = cn / CPS, kc = cn % CPS;
            const float* An = (seg == 0) ? A0 : ((seg == 1) ? A1 : A2);
            const float* Bn = (seg == 0) ? B0 : ((seg == 1) ? B1 : B2);
            An += (long long)kc * KC;
            Bn += (long long)kc * KC;
#pragma unroll
            for (int i = 0; i < 8; ++i) {
                av[i] = *(const float2*)(An + goff[i]);
                bv[i] = *(const float2*)(Bn + goff[i]);
            }
        }
        __syncthreads();

        const uint32_t base = smb + s * (STW * 4);
        uint32_t bh[4][4], bl[4][4];
#pragma unroll
        for (int n = 0; n < 4; ++n) {
            const uint32_t boff = ((wn * 4 + n) << 9) + lane * 16;
            lds128(bh[n], base + BH * 4 + boff);
            lds128(bl[n], base + BL * 4 + boff);
        }
#pragma unroll
        for (int kt = 0; kt < 2; ++kt) {
            uint32_t ah[4][4], al[4][4];
#pragma unroll
            for (int m = 0; m < 4; ++m) {
                const uint32_t aoff = ((((wm * 4 + m) * 2) + kt) << 9) + lane * 16;
                lds128(ah[m], base + aoff);
                if (TERMS == 3) lds128(al[m], base + AL * 4 + aoff);
            }
            // term hh
#pragma unroll
            for (int m = 0; m < 4; ++m)
#pragma unroll
                for (int n = 0; n < 4; ++n)
                    mma16816(acc[m][n], ah[m], bh[n][kt * 2], bh[n][kt * 2 + 1]);
            // term hl
#pragma unroll
            for (int m = 0; m < 4; ++m)
#pragma unroll
                for (int n = 0; n < 4; ++n)
                    mma16816(acc[m][n], ah[m], bl[n][kt * 2], bl[n][kt * 2 + 1]);
            // term lh (3-term only)
            if (TERMS == 3) {
#pragma unroll
                for (int m = 0; m < 4; ++m)
#pragma unroll
                    for (int n = 0; n < 4; ++n)
                        mma16816(acc[m][n], al[m], bh[n][kt * 2], bh[n][kt * 2 + 1]);
            }
        }
    }
}

// ---------------- encoder (2-term now) ----------------
__global__ __launch_bounds__(256) void encoder_mma(const float* __restrict__ resid,  // [L,B,D]
                                                   const float* __restrict__ enc_w,  // [L,F,D]
                                                   const float* __restrict__ enc_b,  // [L,F]
                                                   float* __restrict__ out) {
    extern __shared__ uint32_t smraw[];
    __shared__ float sbias[128];
    __shared__ float s_sp[8];
    __shared__ int   s_cnt[8];

    const int tid = threadIdx.x;
    const int l   = blockIdx.z;
    const int m0  = blockIdx.y * 128;
    const int n0  = blockIdx.x * 128;

    if (tid < 128) sbias[tid] = enc_b[(long long)l * FNUM + n0 + tid];

    float acc[4][4][4];
#pragma unroll
    for (int m = 0; m < 4; ++m)
#pragma unroll
        for (int n = 0; n < 4; ++n)
#pragma unroll
            for (int q = 0; q < 4; ++q) acc[m][n][q] = 0.0f;

    const float* A = resid + ((long long)l * BNUM + m0) * DNUM;
    const float* W = enc_w + ((long long)l * FNUM + n0) * DNUM;
    run_gemm<DNUM / KC, 2>(smraw, smem_u32(smraw), A, A, A, W, W, W, 1, DNUM, acc);

    const int lane = tid & 31, wid = tid >> 5;
    const int wm = wid >> 2, wn = wid & 3;
    const int g = lane >> 2, tt = lane & 3;

    float sp = 0.0f;
    int   cnt = 0;
#pragma unroll
    for (int m = 0; m < 4; ++m) {
        const int r0 = m0 + wm * 64 + m * 16 + g;
#pragma unroll
        for (int n = 0; n < 4; ++n) {
            const int cl  = wn * 32 + n * 8 + tt * 2;
            const float b0 = sbias[cl], b1 = sbias[cl + 1];
            float x0 = fmaxf(acc[m][n][0] + b0, 0.0f);
            float x1 = fmaxf(acc[m][n][1] + b1, 0.0f);
            float x2 = fmaxf(acc[m][n][2] + b0, 0.0f);
            float x3 = fmaxf(acc[m][n][3] + b1, 0.0f);
            sp  += (x0 + x1) + (x2 + x3);
            cnt += (x0 > 0.0f) + (x1 > 0.0f) + (x2 > 0.0f) + (x3 > 0.0f);
            float* p0 = out + FEATS_OFF + ((long long)l * BNUM + r0) * FNUM + n0 + cl;
            float* p1 = out + FEATS_OFF + ((long long)l * BNUM + r0 + 8) * FNUM + n0 + cl;
            *(float2*)p0 = make_float2(x0, x1);
            *(float2*)p1 = make_float2(x2, x3);
        }
    }
#pragma unroll
    for (int o = 16; o > 0; o >>= 1) {
        sp  += __shfl_down_sync(0xffffffffu, sp, o);
        cnt += __shfl_down_sync(0xffffffffu, cnt, o);
    }
    if (lane == 0) { s_sp[wid] = sp; s_cnt[wid] = cnt; }
    __syncthreads();
    if (tid == 0) {
        float tsp = 0.0f; int tc = 0;
        for (int w = 0; w < 8; ++w) { tsp += s_sp[w]; tc += s_cnt[w]; }
        atomicAdd(&g_sp_sum, (double)tsp);
        atomicAdd(&g_cnt[l], (unsigned long long)tc);
    }
}

// ---------------- decoder (2-term; t descending) ----------------
__global__ __launch_bounds__(256) void decoder_mma(const float* __restrict__ feats,  // [L,B,F]
                                                   const float* __restrict__ dec_w,  // [P,D,F]
                                                   const float* __restrict__ tgt,    // [L,B,D]
                                                   float* __restrict__ out) {
    extern __shared__ uint32_t smraw[];
    __shared__ float s_sq[8];

    const int tid = threadIdx.x;
    const int bid = blockIdx.x;
    const int t   = 7 - (bid >> 6);
    const int rem = bid & 63;
    const int m0  = (rem >> 3) * 128;
    const int n0  = (rem & 7) * 128;

    float acc[4][4][4];
#pragma unroll
    for (int m = 0; m < 4; ++m)
#pragma unroll
        for (int n = 0; n < 4; ++n)
#pragma unroll
            for (int q = 0; q < 4; ++q) acc[m][n][q] = 0.0f;

    const int s_lo = (t >= 2) ? (t - 2) : 0;
    const int nseg = t - s_lo + 1;
    const float* As[3]; const float* Bs[3];
#pragma unroll
    for (int i = 0; i < 3; ++i) {
        const int s    = (s_lo + i <= t) ? (s_lo + i) : t;
        const int base = (s <= 5) ? (3 * s) : (2 * s + 6);
        const int p    = base + (t - s);
        As[i] = feats + ((long long)s * BNUM + m0) * FNUM;
        Bs[i] = dec_w + ((long long)p * DNUM + n0) * FNUM;
    }
    run_gemm<FNUM / KC, 2>(smraw, smem_u32(smraw), As[0], As[1], As[2],
                           Bs[0], Bs[1], Bs[2], nseg, FNUM, acc);

    const int lane = tid & 31, wid = tid >> 5;
    const int wm = wid >> 2, wn = wid & 3;
    const int g = lane >> 2, tt = lane & 3;

    float sq = 0.0f;
#pragma unroll
    for (int m = 0; m < 4; ++m) {
        const int r0 = m0 + wm * 64 + m * 16 + g;
#pragma unroll
        for (int n = 0; n < 4; ++n) {
            const int col = n0 + wn * 32 + n * 8 + tt * 2;
            const long long row0 = (long long)t * BNUM + r0;
            const long long row1 = row0 + 8;
            float2 t0 = *(const float2*)(tgt + row0 * DNUM + col);
            float2 t1 = *(const float2*)(tgt + row1 * DNUM + col);
            const float v0 = acc[m][n][0], v1 = acc[m][n][1];
            const float v2 = acc[m][n][2], v3 = acc[m][n][3];
            float d0 = v0 - t0.x, d1 = v1 - t0.y, d2 = v2 - t1.x, d3 = v3 - t1.y;
            sq = fmaf(d0, d0, sq); sq = fmaf(d1, d1, sq);
            sq = fmaf(d2, d2, sq); sq = fmaf(d3, d3, sq);
            *(float2*)(out + row0 * DNUM + col) = make_float2(v0, v1);
            *(float2*)(out + row1 * DNUM + col) = make_float2(v2, v3);
        }
    }
#pragma unroll
    for (int o = 16; o > 0; o >>= 1) sq += __shfl_down_sync(0xffffffffu, sq, o);
    if (lane == 0) s_sq[wid] = sq;
    __syncthreads();
    if (tid == 0) {
        float tsq = 0.0f;
        for (int w = 0; w < 8; ++w) tsq += s_sq[w];
        atomicAdd(&g_sq_sum, (double)tsq);
    }
}

// ---------------- finalize scalars ----------------
__global__ void finalize_kernel(float* __restrict__ out) {
    const int tid = threadIdx.x;
    if (tid == 0) {
        double rl = g_sq_sum / ((double)LNUM * (double)BNUM * (double)DNUM);
        double sl = 1e-4 * (g_sp_sum / ((double)LNUM * (double)BNUM * (double)FNUM));
        out[LOSS_OFF + 0] = (float)(rl + sl);
        out[LOSS_OFF + 1] = (float)rl;
        out[LOSS_OFF + 2] = (float)sl;
    }
    if (tid < LNUM) out[LOSS_OFF + 3 + tid] = (float)((double)g_cnt[tid] / (double)BNUM);
}

// ---------------- entry point ----------------
#define SMEM_2T (2 * 6144 * 4)   // 48 KB (2-term stages)

extern "C" void kernel_launch(void* const* d_in, const int* in_sizes, int n_in,
                              void* d_out, int out_size) {
    (void)in_sizes; (void)n_in; (void)out_size;
    const float* resid   = (const float*)d_in[0];
    const float* targets = (const float*)d_in[1];
    const float* enc_w   = (const float*)d_in[2];
    const float* enc_b   = (const float*)d_in[3];
    const float* dec_w   = (const float*)d_in[4];
    float* out = (float*)d_out;

    static bool attr_done = false;
    if (!attr_done) {
        cudaFuncSetAttribute(encoder_mma, cudaFuncAttributeMaxDynamicSharedMemorySize, SMEM_2T);
        cudaFuncSetAttribute(decoder_mma, cudaFuncAttributeMaxDynamicSharedMemorySize, SMEM_2T);
        attr_done = true;
    }

    init_acc_kernel<<<1, 1>>>();

    dim3 genc(FNUM / 128, BNUM / 128, LNUM);  // (64, 8, 8)
    encoder_mma<<<genc, 256, SMEM_2T>>>(resid, enc_w, enc_b, out);

    decoder_mma<<<512, 256, SMEM_2T>>>(out + FEATS_OFF, dec_w, targets, out);

    finalize_kernel<<<1, 32>>>(out);
}